// round 2
// baseline (speedup 1.0000x reference)
#include <cuda_runtime.h>
#include <math_constants.h>

namespace {
constexpr int B = 4, S = 2048, D = 512, H = 8, HD = 64;
constexpr int M = B * S;  // 8192 rows
constexpr float SLOPE = 0.01f;
constexpr float LN_EPS = 1e-5f;
}

// ---------------- scratch (no allocations allowed) ----------------
__device__ float g_fr[M * D];    // h @ Wr          [B*S, H*HD]
__device__ float g_rk[M * D];    // rh @ Wrs        [B*S, H*RL]
__device__ float g_rq[M * D];    // rh @ Wrt        [B*S, H*RL]
__device__ float g_sr[B * H * S];// leaky(fr) . ar  [B*H*S]
__device__ float g_ctx[M * D];   // attention out   [B*S, H*HD]
__device__ float g_fh[M * D];    // ctx @ Wf        [B*S, D]

// ---------------- generic tiled SGEMM: C[M,512] = A[M,K] @ W[K,512] ----------------
// 64x64 tile, BK=16, 256 threads, 4x4 microtile per thread.
template <int K>
__global__ void __launch_bounds__(256) sgemm_kernel(const float* __restrict__ A,
                                                    const float* __restrict__ W,
                                                    float* __restrict__ C) {
    __shared__ float As[16][68];   // transposed A tile, padded (store-conflict relief)
    __shared__ float Bs[16][64];
    const int tid = threadIdx.x;
    const int tx = tid & 15, ty = tid >> 4;
    const int m0 = blockIdx.y * 64, n0 = blockIdx.x * 64;
    float acc[4][4] = {};
    for (int k0 = 0; k0 < K; k0 += 16) {
        {   // A tile 64x16 -> As[k][m] (one float4 per thread)
            int r = tid >> 2;
            int kq = (tid & 3) * 4;
            const float4 a4 = *reinterpret_cast<const float4*>(&A[(m0 + r) * K + k0 + kq]);
            As[kq + 0][r] = a4.x; As[kq + 1][r] = a4.y;
            As[kq + 2][r] = a4.z; As[kq + 3][r] = a4.w;
        }
        {   // B tile 16x64 (one float4 per thread)
            int kk = tid >> 4;
            int c = (tid & 15) * 4;
            *reinterpret_cast<float4*>(&Bs[kk][c]) =
                *reinterpret_cast<const float4*>(&W[(k0 + kk) * D + n0 + c]);
        }
        __syncthreads();
#pragma unroll
        for (int kk = 0; kk < 16; kk++) {
            float a[4];
#pragma unroll
            for (int i = 0; i < 4; i++) a[i] = As[kk][ty * 4 + i];
            const float4 b4 = *reinterpret_cast<const float4*>(&Bs[kk][tx * 4]);
            const float bb[4] = {b4.x, b4.y, b4.z, b4.w};
#pragma unroll
            for (int i = 0; i < 4; i++)
#pragma unroll
                for (int j = 0; j < 4; j++) acc[i][j] += a[i] * bb[j];
        }
        __syncthreads();
    }
#pragma unroll
    for (int i = 0; i < 4; i++) {
        float4 o = make_float4(acc[i][0], acc[i][1], acc[i][2], acc[i][3]);
        *reinterpret_cast<float4*>(&C[(m0 + ty * 4 + i) * D + n0 + tx * 4]) = o;
    }
}

// ---------------- per-key additive bias: sr[b,h,t] = sum_d leaky(fr) * ar[d] ----------------
__global__ void __launch_bounds__(256) sr_kernel(const float* __restrict__ fr,
                                                 const float* __restrict__ ar,
                                                 float* __restrict__ srb) {
    const int lane = threadIdx.x & 31;
    const int row = blockIdx.x * 8 + (threadIdx.x >> 5);  // over B*H*S
    const int b = row / (H * S);
    const int hh = (row / S) % H;
    const int t = row % S;
    const float* p = fr + (b * S + t) * D + hh * HD;
    float acc = 0.f;
#pragma unroll
    for (int d = lane; d < HD; d += 32) {
        float v = p[d];
        v = (v >= 0.f) ? v : SLOPE * v;
        acc += v * ar[d];
    }
#pragma unroll
    for (int o = 16; o; o >>= 1) acc += __shfl_xor_sync(0xffffffffu, acc, o);
    if (lane == 0) srb[row] = acc;
}

// ---------------- fused flash attention ----------------
// P = softmax_t( rk[s]·rq[t] + sr[t] );  ctx[s] = P @ fr
// Block = (b, h, 64-row Q tile). 256 threads, 4x4 microtiles.
// Row softmax stats reduced with 16-lane shfl butterflies (row owners = half-warp).
__global__ void __launch_bounds__(256) flash_kernel(const float* __restrict__ rk,
                                                    const float* __restrict__ rq,
                                                    const float* __restrict__ fr,
                                                    const float* __restrict__ srb,
                                                    float* __restrict__ ctx) {
    extern __shared__ float sm[];
    float* Qs  = sm;                 // 64*64
    float* KPs = sm + 64 * 64;       // 64*65, K tile then reused as P tile
    float* Vs  = KPs + 64 * 65;      // 64*64
    const int b = blockIdx.z, h = blockIdx.y;
    const int q0 = blockIdx.x * 64;
    const int tid = threadIdx.x;
    const int tx = tid & 15, ty = tid >> 4;

#pragma unroll
    for (int i = tid; i < 64 * 64; i += 256) {
        int r = i >> 6, d = i & 63;
        Qs[r * 64 + d] = rk[(b * S + q0 + r) * D + h * HD + d];
    }

    float mrow[4], lrow[4], acc[4][4];
#pragma unroll
    for (int i = 0; i < 4; i++) {
        mrow[i] = -CUDART_INF_F;
        lrow[i] = 0.f;
#pragma unroll
        for (int j = 0; j < 4; j++) acc[i][j] = 0.f;
    }

    const float* sr_base = srb + (b * H + h) * S;

    for (int t0 = 0; t0 < S; t0 += 64) {
#pragma unroll
        for (int i = tid; i < 64 * 64; i += 256) {
            int r = i >> 6, d = i & 63;
            int g = (b * S + t0 + r) * D + h * HD + d;
            KPs[r * 65 + d] = rq[g];
            Vs[r * 64 + d] = fr[g];
        }
        __syncthreads();

        // S = Q @ K^T  (rows ty*4+i, cols tx*4+j)
        float sv[4][4] = {};
#pragma unroll 16
        for (int d = 0; d < 64; d++) {
            float q[4], k[4];
#pragma unroll
            for (int i = 0; i < 4; i++) q[i] = Qs[(ty * 4 + i) * 64 + d];
#pragma unroll
            for (int j = 0; j < 4; j++) k[j] = KPs[(tx * 4 + j) * 65 + d];
#pragma unroll
            for (int i = 0; i < 4; i++)
#pragma unroll
                for (int j = 0; j < 4; j++) sv[i][j] += q[i] * k[j];
        }
        // + per-key bias
#pragma unroll
        for (int j = 0; j < 4; j++) {
            const float kb = __ldg(&sr_base[t0 + tx * 4 + j]);
#pragma unroll
            for (int i = 0; i < 4; i++) sv[i][j] += kb;
        }
        // online softmax update (16-lane butterfly keeps each row inside a half-warp)
#pragma unroll
        for (int i = 0; i < 4; i++) {
            float v = fmaxf(fmaxf(sv[i][0], sv[i][1]), fmaxf(sv[i][2], sv[i][3]));
#pragma unroll
            for (int o = 1; o < 16; o <<= 1) v = fmaxf(v, __shfl_xor_sync(0xffffffffu, v, o));
            const float mn = fmaxf(mrow[i], v);
            const float scale = __expf(mrow[i] - mn);
            float lt = 0.f;
#pragma unroll
            for (int j = 0; j < 4; j++) { sv[i][j] = __expf(sv[i][j] - mn); lt += sv[i][j]; }
#pragma unroll
            for (int o = 1; o < 16; o <<= 1) lt += __shfl_xor_sync(0xffffffffu, lt, o);
            lrow[i] = lrow[i] * scale + lt;
            mrow[i] = mn;
#pragma unroll
            for (int j = 0; j < 4; j++) acc[i][j] *= scale;
        }
        __syncthreads();  // everyone done reading K before P overwrites it
#pragma unroll
        for (int i = 0; i < 4; i++)
#pragma unroll
            for (int j = 0; j < 4; j++)
                KPs[(ty * 4 + i) * 65 + tx * 4 + j] = sv[i][j];
        __syncthreads();
        // acc += P @ V
#pragma unroll 16
        for (int t = 0; t < 64; t++) {
            float p[4];
#pragma unroll
            for (int i = 0; i < 4; i++) p[i] = KPs[(ty * 4 + i) * 65 + t];
            const float4 v4 = *reinterpret_cast<const float4*>(&Vs[t * 64 + tx * 4]);
#pragma unroll
            for (int i = 0; i < 4; i++) {
                acc[i][0] += p[i] * v4.x;
                acc[i][1] += p[i] * v4.y;
                acc[i][2] += p[i] * v4.z;
                acc[i][3] += p[i] * v4.w;
            }
        }
        __syncthreads();  // done with P/V before next tile load
    }

#pragma unroll
    for (int i = 0; i < 4; i++) {
        const float inv = 1.f / lrow[i];
        float4 o = make_float4(acc[i][0] * inv, acc[i][1] * inv,
                               acc[i][2] * inv, acc[i][3] * inv);
        *reinterpret_cast<float4*>(
            &ctx[(b * S + q0 + ty * 4 + i) * D + h * HD + tx * 4]) = o;
    }
}

// ---------------- residual + LayerNorm, one block per row ----------------
__global__ void __launch_bounds__(256) ln_kernel(const float* __restrict__ hin,
                                                 const float* __restrict__ fh,
                                                 const float* __restrict__ g,
                                                 const float* __restrict__ be,
                                                 float* __restrict__ out) {
    const int row = blockIdx.x;
    const int tid = threadIdx.x;
    const float x0 = hin[row * D + tid] + fh[row * D + tid];
    const float x1 = hin[row * D + tid + 256] + fh[row * D + tid + 256];
    float s = x0 + x1, q = x0 * x0 + x1 * x1;
#pragma unroll
    for (int o = 16; o; o >>= 1) {
        s += __shfl_xor_sync(0xffffffffu, s, o);
        q += __shfl_xor_sync(0xffffffffu, q, o);
    }
    __shared__ float sh_s[8], sh_q[8];
    if ((tid & 31) == 0) { sh_s[tid >> 5] = s; sh_q[tid >> 5] = q; }
    __syncthreads();
    float ts = 0.f, tq = 0.f;
#pragma unroll
    for (int w = 0; w < 8; w++) { ts += sh_s[w]; tq += sh_q[w]; }
    const float mu = ts * (1.f / (float)D);
    const float var = tq * (1.f / (float)D) - mu * mu;
    const float inv = rsqrtf(var + LN_EPS);
    out[row * D + tid] = (x0 - mu) * inv * g[tid] + be[tid];
    out[row * D + tid + 256] = (x1 - mu) * inv * g[tid + 256] + be[tid + 256];
}

// ---------------- launch ----------------
extern "C" void kernel_launch(void* const* d_in, const int* in_sizes, int n_in,
                              void* d_out, int out_size) {
    // metadata order: h, rh, Wl, Wr, al, ar, Wrs, Wrt, Wf, ln_g, ln_b
    const float* h   = (const float*)d_in[0];
    const float* rh  = (const float*)d_in[1];
    // d_in[2] = Wl, d_in[4] = al: mathematically dead (row-constant logit cancels in softmax)
    const float* Wr  = (const float*)d_in[3];
    const float* ar  = (const float*)d_in[5];
    const float* Wrs = (const float*)d_in[6];
    const float* Wrt = (const float*)d_in[7];
    const float* Wf  = (const float*)d_in[8];
    const float* lng = (const float*)d_in[9];
    const float* lnb = (const float*)d_in[10];
    float* out = (float*)d_out;

    float *fr, *rk, *rq, *srb, *ctx, *fh;
    cudaGetSymbolAddress((void**)&fr,  g_fr);
    cudaGetSymbolAddress((void**)&rk,  g_rk);
    cudaGetSymbolAddress((void**)&rq,  g_rq);
    cudaGetSymbolAddress((void**)&srb, g_sr);
    cudaGetSymbolAddress((void**)&ctx, g_ctx);
    cudaGetSymbolAddress((void**)&fh,  g_fh);

    const dim3 gemm_grid(D / 64, M / 64);
    sgemm_kernel<512><<<gemm_grid, 256>>>(h, Wr, fr);
    sgemm_kernel<64><<<gemm_grid, 256>>>(rh, Wrs, rk);
    sgemm_kernel<64><<<gemm_grid, 256>>>(rh, Wrt, rq);
    sr_kernel<<<(B * H * S) / 8, 256>>>(fr, ar, srb);

    constexpr int FLASH_SMEM = (64 * 64 + 64 * 65 + 64 * 64) * (int)sizeof(float);  // 49408 B
    cudaFuncSetAttribute(flash_kernel, cudaFuncAttributeMaxDynamicSharedMemorySize, FLASH_SMEM);
    flash_kernel<<<dim3(S / 64, H, B), 256, FLASH_SMEM>>>(rk, rq, fr, srb, ctx);

    sgemm_kernel<512><<<gemm_grid, 256>>>(ctx, Wf, fh);
    ln_kernel<<<M, 256>>>(h, fh, lng, lnb, out);
}

// round 3
// speedup vs baseline: 2.0982x; 2.0982x over previous
#include <cuda_runtime.h>
#include <cuda_fp16.h>
#include <math_constants.h>

namespace {
constexpr int B = 4, S = 2048, D = 512, H = 8, HD = 64;
constexpr int M = B * S;  // 8192 rows
constexpr float SLOPE = 0.01f;
constexpr float LN_EPS = 1e-5f;
}

// ---------------- scratch (no allocations allowed) ----------------
__device__ float g_fr[M * D];    // h @ Wr          [B*S, H*HD]
__device__ float g_rk[M * D];    // rh @ Wrs        [B*S, H*RL]
__device__ float g_rq[M * D];    // rh @ Wrt        [B*S, H*RL]
__device__ float g_sr[B * H * S];// leaky(fr) . ar  [B*H*S]
__device__ float g_ctx[M * D];   // attention out   [B*S, H*HD]
__device__ float g_fh[M * D];    // ctx @ Wf        [B*S, D]

// ---------------- generic tiled SGEMM: C[M,512] = A[M,K] @ W[K,512] ----------------
template <int K>
__global__ void __launch_bounds__(256) sgemm_kernel(const float* __restrict__ A,
                                                    const float* __restrict__ W,
                                                    float* __restrict__ C) {
    __shared__ float As[16][68];
    __shared__ float Bs[16][64];
    const int tid = threadIdx.x;
    const int tx = tid & 15, ty = tid >> 4;
    const int m0 = blockIdx.y * 64, n0 = blockIdx.x * 64;
    float acc[4][4] = {};
    for (int k0 = 0; k0 < K; k0 += 16) {
        {
            int r = tid >> 2;
            int kq = (tid & 3) * 4;
            const float4 a4 = *reinterpret_cast<const float4*>(&A[(m0 + r) * K + k0 + kq]);
            As[kq + 0][r] = a4.x; As[kq + 1][r] = a4.y;
            As[kq + 2][r] = a4.z; As[kq + 3][r] = a4.w;
        }
        {
            int kk = tid >> 4;
            int c = (tid & 15) * 4;
            *reinterpret_cast<float4*>(&Bs[kk][c]) =
                *reinterpret_cast<const float4*>(&W[(k0 + kk) * D + n0 + c]);
        }
        __syncthreads();
#pragma unroll
        for (int kk = 0; kk < 16; kk++) {
            float a[4];
#pragma unroll
            for (int i = 0; i < 4; i++) a[i] = As[kk][ty * 4 + i];
            const float4 b4 = *reinterpret_cast<const float4*>(&Bs[kk][tx * 4]);
            const float bb[4] = {b4.x, b4.y, b4.z, b4.w};
#pragma unroll
            for (int i = 0; i < 4; i++)
#pragma unroll
                for (int j = 0; j < 4; j++) acc[i][j] += a[i] * bb[j];
        }
        __syncthreads();
    }
#pragma unroll
    for (int i = 0; i < 4; i++) {
        float4 o = make_float4(acc[i][0], acc[i][1], acc[i][2], acc[i][3]);
        *reinterpret_cast<float4*>(&C[(m0 + ty * 4 + i) * D + n0 + tx * 4]) = o;
    }
}

// ---------------- per-key additive bias ----------------
__global__ void __launch_bounds__(256) sr_kernel(const float* __restrict__ fr,
                                                 const float* __restrict__ ar,
                                                 float* __restrict__ srb) {
    const int lane = threadIdx.x & 31;
    const int row = blockIdx.x * 8 + (threadIdx.x >> 5);
    const int b = row / (H * S);
    const int hh = (row / S) % H;
    const int t = row % S;
    const float* p = fr + (b * S + t) * D + hh * HD;
    float acc = 0.f;
#pragma unroll
    for (int d = lane; d < HD; d += 32) {
        float v = p[d];
        v = (v >= 0.f) ? v : SLOPE * v;
        acc += v * ar[d];
    }
#pragma unroll
    for (int o = 16; o; o >>= 1) acc += __shfl_xor_sync(0xffffffffu, acc, o);
    if (lane == 0) srb[row] = acc;
}

// ---------------- tensor-core flash attention ----------------
// QK: tf32 mma.m16n8k8; PV: fp16 mma.m16n8k16 (S C-frag == P A-frag layout identity).
// Block: 8 warps x 16 q-rows = 128 q rows per (b,h). Key tile = 64.
__device__ __forceinline__ unsigned f2tf32(float f) {
    unsigned u;
    asm("cvt.rna.tf32.f32 %0, %1;" : "=r"(u) : "f"(f));
    return u;
}

__device__ __forceinline__ void mma_tf32(float& d0, float& d1, float& d2, float& d3,
                                         unsigned a0, unsigned a1, unsigned a2, unsigned a3,
                                         unsigned b0, unsigned b1) {
    asm volatile(
        "mma.sync.aligned.m16n8k8.row.col.f32.tf32.tf32.f32 "
        "{%0,%1,%2,%3}, {%4,%5,%6,%7}, {%8,%9}, {%0,%1,%2,%3};"
        : "+f"(d0), "+f"(d1), "+f"(d2), "+f"(d3)
        : "r"(a0), "r"(a1), "r"(a2), "r"(a3), "r"(b0), "r"(b1));
}

__device__ __forceinline__ void mma_f16(float& d0, float& d1, float& d2, float& d3,
                                        unsigned a0, unsigned a1, unsigned a2, unsigned a3,
                                        unsigned b0, unsigned b1) {
    asm volatile(
        "mma.sync.aligned.m16n8k16.row.col.f32.f16.f16.f32 "
        "{%0,%1,%2,%3}, {%4,%5,%6,%7}, {%8,%9}, {%0,%1,%2,%3};"
        : "+f"(d0), "+f"(d1), "+f"(d2), "+f"(d3)
        : "r"(a0), "r"(a1), "r"(a2), "r"(a3), "r"(b0), "r"(b1));
}

__global__ void __launch_bounds__(256) flash_mma_kernel(const float* __restrict__ rk,
                                                        const float* __restrict__ rq,
                                                        const float* __restrict__ fr,
                                                        const float* __restrict__ srb,
                                                        float* __restrict__ ctx) {
    // pad 68: B-frag access bank = (4*g + tg) -> all 32 banks, conflict-free
    __shared__ unsigned Ks[64][68];   // K tile (rq head), tf32 bits
    __shared__ unsigned Vt[64][36];   // V^T tile as half2: Vt[d][tpair] = (V[2tp][d], V[2tp+1][d])
    __shared__ float srs[64];

    const int b = blockIdx.z, h = blockIdx.y;
    const int q0 = blockIdx.x * 128;
    const int tid = threadIdx.x;
    const int wid = tid >> 5, lane = tid & 31;
    const int g = lane >> 2, tg = lane & 3;   // group row / thread-in-group

    // ---- Q fragments (A of QK), held in registers for the whole key loop ----
    unsigned qf[8][4];
    {
        const float* qb = rk + (size_t)(b * S + q0 + wid * 16) * D + h * HD;
#pragma unroll
        for (int kk = 0; kk < 8; kk++) {
            qf[kk][0] = f2tf32(__ldg(qb + g * D + 8 * kk + tg));
            qf[kk][1] = f2tf32(__ldg(qb + (g + 8) * D + 8 * kk + tg));
            qf[kk][2] = f2tf32(__ldg(qb + g * D + 8 * kk + tg + 4));
            qf[kk][3] = f2tf32(__ldg(qb + (g + 8) * D + 8 * kk + tg + 4));
        }
    }

    float oacc[8][4];
#pragma unroll
    for (int j = 0; j < 8; j++)
#pragma unroll
        for (int i = 0; i < 4; i++) oacc[j][i] = 0.f;
    float m0 = -CUDART_INF_F, m1 = -CUDART_INF_F, l0 = 0.f, l1 = 0.f;

    const float* sr_base = srb + (size_t)(b * H + h) * S;

    for (int t0 = 0; t0 < S; t0 += 64) {
        // ---- stage K tile (tf32) ----
        {
            int t = tid >> 2;
            int cq = (tid & 3) * 16;
            const float* kp = rq + (size_t)(b * S + t0 + t) * D + h * HD + cq;
#pragma unroll
            for (int c = 0; c < 16; c += 4) {
                const float4 v = *reinterpret_cast<const float4*>(kp + c);
                Ks[t][cq + c + 0] = f2tf32(v.x);
                Ks[t][cq + c + 1] = f2tf32(v.y);
                Ks[t][cq + c + 2] = f2tf32(v.z);
                Ks[t][cq + c + 3] = f2tf32(v.w);
            }
        }
        // ---- stage V^T tile (half2 pairs along t) ----
        {
            int tp = tid >> 3;            // 0..31 key pair
            int dq = (tid & 7) * 8;       // 8 d-columns
            const float* vp = fr + (size_t)(b * S + t0 + 2 * tp) * D + h * HD + dq;
            const float4 e0 = *reinterpret_cast<const float4*>(vp);
            const float4 e1 = *reinterpret_cast<const float4*>(vp + 4);
            const float4 o0 = *reinterpret_cast<const float4*>(vp + D);
            const float4 o1 = *reinterpret_cast<const float4*>(vp + D + 4);
            const float ev[8] = {e0.x, e0.y, e0.z, e0.w, e1.x, e1.y, e1.z, e1.w};
            const float ov[8] = {o0.x, o0.y, o0.z, o0.w, o1.x, o1.y, o1.z, o1.w};
#pragma unroll
            for (int k = 0; k < 8; k++) {
                __half2 hv = __floats2half2_rn(ev[k], ov[k]);
                Vt[dq + k][tp] = *reinterpret_cast<unsigned*>(&hv);
            }
        }
        if (tid < 64) srs[tid] = sr_base[t0 + tid];
        __syncthreads();

        // ---- S = Q @ K^T (tf32 mma) ----
        float sf[8][4];
#pragma unroll
        for (int jn = 0; jn < 8; jn++) {
            sf[jn][0] = sf[jn][1] = sf[jn][2] = sf[jn][3] = 0.f;
#pragma unroll
            for (int kk = 0; kk < 8; kk++) {
                const unsigned b0 = Ks[8 * jn + g][8 * kk + tg];
                const unsigned b1 = Ks[8 * jn + g][8 * kk + tg + 4];
                mma_tf32(sf[jn][0], sf[jn][1], sf[jn][2], sf[jn][3],
                         qf[kk][0], qf[kk][1], qf[kk][2], qf[kk][3], b0, b1);
            }
        }

        // ---- bias + online softmax ----
        float mx0 = -CUDART_INF_F, mx1 = -CUDART_INF_F;
#pragma unroll
        for (int jn = 0; jn < 8; jn++) {
            const float b0 = srs[8 * jn + 2 * tg];
            const float b1 = srs[8 * jn + 2 * tg + 1];
            sf[jn][0] += b0; sf[jn][1] += b1;
            sf[jn][2] += b0; sf[jn][3] += b1;
            mx0 = fmaxf(mx0, fmaxf(sf[jn][0], sf[jn][1]));
            mx1 = fmaxf(mx1, fmaxf(sf[jn][2], sf[jn][3]));
        }
#pragma unroll
        for (int o = 1; o < 4; o <<= 1) {
            mx0 = fmaxf(mx0, __shfl_xor_sync(0xffffffffu, mx0, o));
            mx1 = fmaxf(mx1, __shfl_xor_sync(0xffffffffu, mx1, o));
        }
        const float nm0 = fmaxf(m0, mx0), nm1 = fmaxf(m1, mx1);
        const float sc0 = __expf(m0 - nm0), sc1 = __expf(m1 - nm1);
        float rs0 = 0.f, rs1 = 0.f;
#pragma unroll
        for (int jn = 0; jn < 8; jn++) {
            sf[jn][0] = __expf(sf[jn][0] - nm0);
            sf[jn][1] = __expf(sf[jn][1] - nm0);
            sf[jn][2] = __expf(sf[jn][2] - nm1);
            sf[jn][3] = __expf(sf[jn][3] - nm1);
            rs0 += sf[jn][0] + sf[jn][1];
            rs1 += sf[jn][2] + sf[jn][3];
        }
#pragma unroll
        for (int o = 1; o < 4; o <<= 1) {
            rs0 += __shfl_xor_sync(0xffffffffu, rs0, o);
            rs1 += __shfl_xor_sync(0xffffffffu, rs1, o);
        }
        l0 = l0 * sc0 + rs0;
        l1 = l1 * sc1 + rs1;
        m0 = nm0; m1 = nm1;
#pragma unroll
        for (int jn = 0; jn < 8; jn++) {
            oacc[jn][0] *= sc0; oacc[jn][1] *= sc0;
            oacc[jn][2] *= sc1; oacc[jn][3] *= sc1;
        }

        // ---- pack P to fp16 A-fragments (layout identity: C frag -> A frag) ----
        unsigned pa[4][4];
#pragma unroll
        for (int kt = 0; kt < 4; kt++) {
            __half2 h0 = __floats2half2_rn(sf[2 * kt][0], sf[2 * kt][1]);
            __half2 h1 = __floats2half2_rn(sf[2 * kt][2], sf[2 * kt][3]);
            __half2 h2 = __floats2half2_rn(sf[2 * kt + 1][0], sf[2 * kt + 1][1]);
            __half2 h3 = __floats2half2_rn(sf[2 * kt + 1][2], sf[2 * kt + 1][3]);
            pa[kt][0] = *reinterpret_cast<unsigned*>(&h0);
            pa[kt][1] = *reinterpret_cast<unsigned*>(&h1);
            pa[kt][2] = *reinterpret_cast<unsigned*>(&h2);
            pa[kt][3] = *reinterpret_cast<unsigned*>(&h3);
        }

        // ---- O += P @ V (fp16 mma) ----
#pragma unroll
        for (int jn = 0; jn < 8; jn++) {
#pragma unroll
            for (int kt = 0; kt < 4; kt++) {
                const unsigned b0 = Vt[8 * jn + g][8 * kt + tg];
                const unsigned b1 = Vt[8 * jn + g][8 * kt + tg + 4];
                mma_f16(oacc[jn][0], oacc[jn][1], oacc[jn][2], oacc[jn][3],
                        pa[kt][0], pa[kt][1], pa[kt][2], pa[kt][3], b0, b1);
            }
        }
        __syncthreads();
    }

    // ---- epilogue: normalize rows, write ctx ----
    const float inv0 = 1.f / l0, inv1 = 1.f / l1;
    float* op = ctx + (size_t)(b * S + q0 + wid * 16 + g) * D + h * HD;
#pragma unroll
    for (int jn = 0; jn < 8; jn++) {
        float2 w0 = make_float2(oacc[jn][0] * inv0, oacc[jn][1] * inv0);
        *reinterpret_cast<float2*>(op + 8 * jn + 2 * tg) = w0;
        float2 w1 = make_float2(oacc[jn][2] * inv1, oacc[jn][3] * inv1);
        *reinterpret_cast<float2*>(op + 8 * D + 8 * jn + 2 * tg) = w1;
    }
}

// ---------------- residual + LayerNorm ----------------
__global__ void __launch_bounds__(256) ln_kernel(const float* __restrict__ hin,
                                                 const float* __restrict__ fh,
                                                 const float* __restrict__ g,
                                                 const float* __restrict__ be,
                                                 float* __restrict__ out) {
    const int row = blockIdx.x;
    const int tid = threadIdx.x;
    const float x0 = hin[row * D + tid] + fh[row * D + tid];
    const float x1 = hin[row * D + tid + 256] + fh[row * D + tid + 256];
    float s = x0 + x1, q = x0 * x0 + x1 * x1;
#pragma unroll
    for (int o = 16; o; o >>= 1) {
        s += __shfl_xor_sync(0xffffffffu, s, o);
        q += __shfl_xor_sync(0xffffffffu, q, o);
    }
    __shared__ float sh_s[8], sh_q[8];
    if ((tid & 31) == 0) { sh_s[tid >> 5] = s; sh_q[tid >> 5] = q; }
    __syncthreads();
    float ts = 0.f, tq = 0.f;
#pragma unroll
    for (int w = 0; w < 8; w++) { ts += sh_s[w]; tq += sh_q[w]; }
    const float mu = ts * (1.f / (float)D);
    const float var = tq * (1.f / (float)D) - mu * mu;
    const float inv = rsqrtf(var + LN_EPS);
    out[row * D + tid] = (x0 - mu) * inv * g[tid] + be[tid];
    out[row * D + tid + 256] = (x1 - mu) * inv * g[tid + 256] + be[tid + 256];
}

// ---------------- launch ----------------
extern "C" void kernel_launch(void* const* d_in, const int* in_sizes, int n_in,
                              void* d_out, int out_size) {
    // metadata order: h, rh, Wl, Wr, al, ar, Wrs, Wrt, Wf, ln_g, ln_b
    const float* h   = (const float*)d_in[0];
    const float* rh  = (const float*)d_in[1];
    // d_in[2] = Wl, d_in[4] = al: dead (row-constant logit cancels in softmax)
    const float* Wr  = (const float*)d_in[3];
    const float* ar  = (const float*)d_in[5];
    const float* Wrs = (const float*)d_in[6];
    const float* Wrt = (const float*)d_in[7];
    const float* Wf  = (const float*)d_in[8];
    const float* lng = (const float*)d_in[9];
    const float* lnb = (const float*)d_in[10];
    float* out = (float*)d_out;

    float *fr, *rk, *rq, *srb, *ctx, *fh;
    cudaGetSymbolAddress((void**)&fr,  g_fr);
    cudaGetSymbolAddress((void**)&rk,  g_rk);
    cudaGetSymbolAddress((void**)&rq,  g_rq);
    cudaGetSymbolAddress((void**)&srb, g_sr);
    cudaGetSymbolAddress((void**)&ctx, g_ctx);
    cudaGetSymbolAddress((void**)&fh,  g_fh);

    const dim3 gemm_grid(D / 64, M / 64);
    sgemm_kernel<512><<<gemm_grid, 256>>>(h, Wr, fr);
    sgemm_kernel<64><<<gemm_grid, 256>>>(rh, Wrs, rk);
    sgemm_kernel<64><<<gemm_grid, 256>>>(rh, Wrt, rq);
    sr_kernel<<<(B * H * S) / 8, 256>>>(fr, ar, srb);

    flash_mma_kernel<<<dim3(S / 128, H, B), 256>>>(rk, rq, fr, srb, ctx);

    sgemm_kernel<512><<<gemm_grid, 256>>>(ctx, Wf, fh);
    ln_kernel<<<M, 256>>>(h, fh, lng, lnb, out);
}

// round 13
// speedup vs baseline: 2.6871x; 1.2807x over previous
#include <cuda_runtime.h>
#include <cuda_fp16.h>
#include <math_constants.h>

namespace {
constexpr int B = 4, S = 2048, D = 512, H = 8, HD = 64;
constexpr int M = B * S;  // 8192 rows
constexpr float SLOPE = 0.01f;
constexpr float LN_EPS = 1e-5f;
}

// ---------------- scratch (no allocations allowed) ----------------
__device__ float g_fr[M * D];    // h @ Wr          [B*S, H*HD]
__device__ float g_rk[M * D];    // rh @ Wrs        [B*S, H*RL]
__device__ float g_rq[M * D];    // rh @ Wrt        [B*S, H*RL]
__device__ float g_sr[B * H * S];// leaky(fr) . ar  [B*H*S]
__device__ float g_ctx[M * D];   // attention out   [B*S, H*HD]
__device__ float g_fh[M * D];    // ctx @ Wf        [B*S, D]

// ---------------- mma helpers ----------------
__device__ __forceinline__ unsigned f2tf32(float f) {
    unsigned u;
    asm("cvt.rna.tf32.f32 %0, %1;" : "=r"(u) : "f"(f));
    return u;
}

__device__ __forceinline__ void mma_tf32(float& d0, float& d1, float& d2, float& d3,
                                         unsigned a0, unsigned a1, unsigned a2, unsigned a3,
                                         unsigned b0, unsigned b1) {
    asm volatile(
        "mma.sync.aligned.m16n8k8.row.col.f32.tf32.tf32.f32 "
        "{%0,%1,%2,%3}, {%4,%5,%6,%7}, {%8,%9}, {%0,%1,%2,%3};"
        : "+f"(d0), "+f"(d1), "+f"(d2), "+f"(d3)
        : "r"(a0), "r"(a1), "r"(a2), "r"(a3), "r"(b0), "r"(b1));
}

__device__ __forceinline__ void mma_f16(float& d0, float& d1, float& d2, float& d3,
                                        unsigned a0, unsigned a1, unsigned a2, unsigned a3,
                                        unsigned b0, unsigned b1) {
    asm volatile(
        "mma.sync.aligned.m16n8k16.row.col.f32.f16.f16.f32 "
        "{%0,%1,%2,%3}, {%4,%5,%6,%7}, {%8,%9}, {%0,%1,%2,%3};"
        : "+f"(d0), "+f"(d1), "+f"(d2), "+f"(d3)
        : "r"(a0), "r"(a1), "r"(a2), "r"(a3), "r"(b0), "r"(b1));
}

// ---------------- tf32 tensor-core GEMM: C[M,512] = A[M,K] @ W[K,512] ----------------
// Block 128x128, 8 warps (2M x 4N), warp tile 64x32. Pad-36 rows -> conflict-free frags.
template <int K>
__global__ void __launch_bounds__(256, 1) gemm_tf32_kernel(const float* __restrict__ A,
                                                           const float* __restrict__ W,
                                                           float* __restrict__ C) {
    __shared__ unsigned As[128][36];   // A tile [m][k], tf32 bits
    __shared__ unsigned Ws[128][36];   // W tile transposed [n][k], tf32 bits
    const int tid = threadIdx.x;
    const int wid = tid >> 5, lane = tid & 31;
    const int g = lane >> 2, tg = lane & 3;
    const int m0 = blockIdx.y * 128, n0 = blockIdx.x * 128;
    const int mw = (wid >> 2) * 64, nw = (wid & 3) * 32;

    float acc[4][4][4] = {};  // [mi][nj][frag]

    for (int k0 = 0; k0 < K; k0 += 32) {
        {   // stage A 128x32 (each thread: 1 row-half = 16 floats)
            const int r = tid >> 1;
            const int cb = (tid & 1) * 16;
            const float* ap = A + (size_t)(m0 + r) * K + k0 + cb;
#pragma unroll
            for (int c = 0; c < 16; c += 4) {
                const float4 v = *reinterpret_cast<const float4*>(ap + c);
                As[r][cb + c + 0] = f2tf32(v.x);
                As[r][cb + c + 1] = f2tf32(v.y);
                As[r][cb + c + 2] = f2tf32(v.z);
                As[r][cb + c + 3] = f2tf32(v.w);
            }
        }
        {   // stage W transposed: Ws[n][kk] (lane kk, conflict-free column store)
            const int kk = tid & 31;
            const int nb = (tid >> 5) * 16;
            const float* wp = W + (size_t)(k0 + kk) * D + n0 + nb;
#pragma unroll
            for (int c = 0; c < 16; c += 4) {
                const float4 v = *reinterpret_cast<const float4*>(wp + c);
                Ws[nb + c + 0][kk] = f2tf32(v.x);
                Ws[nb + c + 1][kk] = f2tf32(v.y);
                Ws[nb + c + 2][kk] = f2tf32(v.z);
                Ws[nb + c + 3][kk] = f2tf32(v.w);
            }
        }
        __syncthreads();
#pragma unroll
        for (int s = 0; s < 4; s++) {
            unsigned af[4][4], bf[4][2];
#pragma unroll
            for (int i = 0; i < 4; i++) {
                af[i][0] = As[mw + 16 * i + g][8 * s + tg];
                af[i][1] = As[mw + 16 * i + g + 8][8 * s + tg];
                af[i][2] = As[mw + 16 * i + g][8 * s + tg + 4];
                af[i][3] = As[mw + 16 * i + g + 8][8 * s + tg + 4];
            }
#pragma unroll
            for (int j = 0; j < 4; j++) {
                bf[j][0] = Ws[nw + 8 * j + g][8 * s + tg];
                bf[j][1] = Ws[nw + 8 * j + g][8 * s + tg + 4];
            }
#pragma unroll
            for (int i = 0; i < 4; i++)
#pragma unroll
                for (int j = 0; j < 4; j++)
                    mma_tf32(acc[i][j][0], acc[i][j][1], acc[i][j][2], acc[i][j][3],
                             af[i][0], af[i][1], af[i][2], af[i][3], bf[j][0], bf[j][1]);
        }
        __syncthreads();
    }
#pragma unroll
    for (int i = 0; i < 4; i++) {
        float* cp0 = C + (size_t)(m0 + mw + 16 * i + g) * D + n0 + nw;
        float* cp1 = cp0 + (size_t)8 * D;
#pragma unroll
        for (int j = 0; j < 4; j++) {
            *reinterpret_cast<float2*>(cp0 + 8 * j + 2 * tg) =
                make_float2(acc[i][j][0], acc[i][j][1]);
            *reinterpret_cast<float2*>(cp1 + 8 * j + 2 * tg) =
                make_float2(acc[i][j][2], acc[i][j][3]);
        }
    }
}

// ---------------- per-key additive bias ----------------
__global__ void __launch_bounds__(256) sr_kernel(const float* __restrict__ fr,
                                                 const float* __restrict__ ar,
                                                 float* __restrict__ srb) {
    const int lane = threadIdx.x & 31;
    const int row = blockIdx.x * 8 + (threadIdx.x >> 5);
    const int b = row / (H * S);
    const int hh = (row / S) % H;
    const int t = row % S;
    const float* p = fr + (b * S + t) * D + hh * HD;
    float acc = 0.f;
#pragma unroll
    for (int d = lane; d < HD; d += 32) {
        float v = p[d];
        v = (v >= 0.f) ? v : SLOPE * v;
        acc += v * ar[d];
    }
#pragma unroll
    for (int o = 16; o; o >>= 1) acc += __shfl_xor_sync(0xffffffffu, acc, o);
    if (lane == 0) srb[row] = acc;
}

// ---------------- tensor-core flash attention ----------------
__global__ void __launch_bounds__(256) flash_mma_kernel(const float* __restrict__ rk,
                                                        const float* __restrict__ rq,
                                                        const float* __restrict__ fr,
                                                        const float* __restrict__ srb,
                                                        float* __restrict__ ctx) {
    __shared__ unsigned Ks[64][68];
    __shared__ unsigned Vt[64][36];
    __shared__ float srs[64];

    const int b = blockIdx.z, h = blockIdx.y;
    const int q0 = blockIdx.x * 128;
    const int tid = threadIdx.x;
    const int wid = tid >> 5, lane = tid & 31;
    const int g = lane >> 2, tg = lane & 3;

    unsigned qf[8][4];
    {
        const float* qb = rk + (size_t)(b * S + q0 + wid * 16) * D + h * HD;
#pragma unroll
        for (int kk = 0; kk < 8; kk++) {
            qf[kk][0] = f2tf32(__ldg(qb + g * D + 8 * kk + tg));
            qf[kk][1] = f2tf32(__ldg(qb + (g + 8) * D + 8 * kk + tg));
            qf[kk][2] = f2tf32(__ldg(qb + g * D + 8 * kk + tg + 4));
            qf[kk][3] = f2tf32(__ldg(qb + (g + 8) * D + 8 * kk + tg + 4));
        }
    }

    float oacc[8][4];
#pragma unroll
    for (int j = 0; j < 8; j++)
#pragma unroll
        for (int i = 0; i < 4; i++) oacc[j][i] = 0.f;
    float m0 = -CUDART_INF_F, m1 = -CUDART_INF_F, l0 = 0.f, l1 = 0.f;

    const float* sr_base = srb + (size_t)(b * H + h) * S;

    for (int t0 = 0; t0 < S; t0 += 64) {
        {
            int t = tid >> 2;
            int cq = (tid & 3) * 16;
            const float* kp = rq + (size_t)(b * S + t0 + t) * D + h * HD + cq;
#pragma unroll
            for (int c = 0; c < 16; c += 4) {
                const float4 v = *reinterpret_cast<const float4*>(kp + c);
                Ks[t][cq + c + 0] = f2tf32(v.x);
                Ks[t][cq + c + 1] = f2tf32(v.y);
                Ks[t][cq + c + 2] = f2tf32(v.z);
                Ks[t][cq + c + 3] = f2tf32(v.w);
            }
        }
        {
            int tp = tid >> 3;
            int dq = (tid & 7) * 8;
            const float* vp = fr + (size_t)(b * S + t0 + 2 * tp) * D + h * HD + dq;
            const float4 e0 = *reinterpret_cast<const float4*>(vp);
            const float4 e1 = *reinterpret_cast<const float4*>(vp + 4);
            const float4 o0 = *reinterpret_cast<const float4*>(vp + D);
            const float4 o1 = *reinterpret_cast<const float4*>(vp + D + 4);
            const float ev[8] = {e0.x, e0.y, e0.z, e0.w, e1.x, e1.y, e1.z, e1.w};
            const float ov[8] = {o0.x, o0.y, o0.z, o0.w, o1.x, o1.y, o1.z, o1.w};
#pragma unroll
            for (int k = 0; k < 8; k++) {
                __half2 hv = __floats2half2_rn(ev[k], ov[k]);
                Vt[dq + k][tp] = *reinterpret_cast<unsigned*>(&hv);
            }
        }
        if (tid < 64) srs[tid] = sr_base[t0 + tid];
        __syncthreads();

        float sf[8][4];
#pragma unroll
        for (int jn = 0; jn < 8; jn++) {
            sf[jn][0] = sf[jn][1] = sf[jn][2] = sf[jn][3] = 0.f;
#pragma unroll
            for (int kk = 0; kk < 8; kk++) {
                const unsigned b0 = Ks[8 * jn + g][8 * kk + tg];
                const unsigned b1 = Ks[8 * jn + g][8 * kk + tg + 4];
                mma_tf32(sf[jn][0], sf[jn][1], sf[jn][2], sf[jn][3],
                         qf[kk][0], qf[kk][1], qf[kk][2], qf[kk][3], b0, b1);
            }
        }

        float mx0 = -CUDART_INF_F, mx1 = -CUDART_INF_F;
#pragma unroll
        for (int jn = 0; jn < 8; jn++) {
            const float b0 = srs[8 * jn + 2 * tg];
            const float b1 = srs[8 * jn + 2 * tg + 1];
            sf[jn][0] += b0; sf[jn][1] += b1;
            sf[jn][2] += b0; sf[jn][3] += b1;
            mx0 = fmaxf(mx0, fmaxf(sf[jn][0], sf[jn][1]));
            mx1 = fmaxf(mx1, fmaxf(sf[jn][2], sf[jn][3]));
        }
#pragma unroll
        for (int o = 1; o < 4; o <<= 1) {
            mx0 = fmaxf(mx0, __shfl_xor_sync(0xffffffffu, mx0, o));
            mx1 = fmaxf(mx1, __shfl_xor_sync(0xffffffffu, mx1, o));
        }
        const float nm0 = fmaxf(m0, mx0), nm1 = fmaxf(m1, mx1);
        const float sc0 = __expf(m0 - nm0), sc1 = __expf(m1 - nm1);
        float rs0 = 0.f, rs1 = 0.f;
#pragma unroll
        for (int jn = 0; jn < 8; jn++) {
            sf[jn][0] = __expf(sf[jn][0] - nm0);
            sf[jn][1] = __expf(sf[jn][1] - nm0);
            sf[jn][2] = __expf(sf[jn][2] - nm1);
            sf[jn][3] = __expf(sf[jn][3] - nm1);
            rs0 += sf[jn][0] + sf[jn][1];
            rs1 += sf[jn][2] + sf[jn][3];
        }
#pragma unroll
        for (int o = 1; o < 4; o <<= 1) {
            rs0 += __shfl_xor_sync(0xffffffffu, rs0, o);
            rs1 += __shfl_xor_sync(0xffffffffu, rs1, o);
        }
        l0 = l0 * sc0 + rs0;
        l1 = l1 * sc1 + rs1;
        m0 = nm0; m1 = nm1;
#pragma unroll
        for (int jn = 0; jn < 8; jn++) {
            oacc[jn][0] *= sc0; oacc[jn][1] *= sc0;
            oacc[jn][2] *= sc1; oacc[jn][3] *= sc1;
        }

        unsigned pa[4][4];
#pragma unroll
        for (int kt = 0; kt < 4; kt++) {
            __half2 h0 = __floats2half2_rn(sf[2 * kt][0], sf[2 * kt][1]);
            __half2 h1 = __floats2half2_rn(sf[2 * kt][2], sf[2 * kt][3]);
            __half2 h2 = __floats2half2_rn(sf[2 * kt + 1][0], sf[2 * kt + 1][1]);
            __half2 h3 = __floats2half2_rn(sf[2 * kt + 1][2], sf[2 * kt + 1][3]);
            pa[kt][0] = *reinterpret_cast<unsigned*>(&h0);
            pa[kt][1] = *reinterpret_cast<unsigned*>(&h1);
            pa[kt][2] = *reinterpret_cast<unsigned*>(&h2);
            pa[kt][3] = *reinterpret_cast<unsigned*>(&h3);
        }

#pragma unroll
        for (int jn = 0; jn < 8; jn++) {
#pragma unroll
            for (int kt = 0; kt < 4; kt++) {
                const unsigned b0 = Vt[8 * jn + g][8 * kt + tg];
                const unsigned b1 = Vt[8 * jn + g][8 * kt + tg + 4];
                mma_f16(oacc[jn][0], oacc[jn][1], oacc[jn][2], oacc[jn][3],
                        pa[kt][0], pa[kt][1], pa[kt][2], pa[kt][3], b0, b1);
            }
        }
        __syncthreads();
    }

    const float inv0 = 1.f / l0, inv1 = 1.f / l1;
    float* op = ctx + (size_t)(b * S + q0 + wid * 16 + g) * D + h * HD;
#pragma unroll
    for (int jn = 0; jn < 8; jn++) {
        float2 w0 = make_float2(oacc[jn][0] * inv0, oacc[jn][1] * inv0);
        *reinterpret_cast<float2*>(op + 8 * jn + 2 * tg) = w0;
        float2 w1 = make_float2(oacc[jn][2] * inv1, oacc[jn][3] * inv1);
        *reinterpret_cast<float2*>(op + 8 * D + 8 * jn + 2 * tg) = w1;
    }
}

// ---------------- residual + LayerNorm ----------------
__global__ void __launch_bounds__(256) ln_kernel(const float* __restrict__ hin,
                                                 const float* __restrict__ fh,
                                                 const float* __restrict__ g,
                                                 const float* __restrict__ be,
                                                 float* __restrict__ out) {
    const int row = blockIdx.x;
    const int tid = threadIdx.x;
    const float x0 = hin[row * D + tid] + fh[row * D + tid];
    const float x1 = hin[row * D + tid + 256] + fh[row * D + tid + 256];
    float s = x0 + x1, q = x0 * x0 + x1 * x1;
#pragma unroll
    for (int o = 16; o; o >>= 1) {
        s += __shfl_xor_sync(0xffffffffu, s, o);
        q += __shfl_xor_sync(0xffffffffu, q, o);
    }
    __shared__ float sh_s[8], sh_q[8];
    if ((tid & 31) == 0) { sh_s[tid >> 5] = s; sh_q[tid >> 5] = q; }
    __syncthreads();
    float ts = 0.f, tq = 0.f;
#pragma unroll
    for (int w = 0; w < 8; w++) { ts += sh_s[w]; tq += sh_q[w]; }
    const float mu = ts * (1.f / (float)D);
    const float var = tq * (1.f / (float)D) - mu * mu;
    const float inv = rsqrtf(var + LN_EPS);
    out[row * D + tid] = (x0 - mu) * inv * g[tid] + be[tid];
    out[row * D + tid + 256] = (x1 - mu) * inv * g[tid + 256] + be[tid + 256];
}

// ---------------- launch ----------------
extern "C" void kernel_launch(void* const* d_in, const int* in_sizes, int n_in,
                              void* d_out, int out_size) {
    // metadata order: h, rh, Wl, Wr, al, ar, Wrs, Wrt, Wf, ln_g, ln_b
    const float* h   = (const float*)d_in[0];
    const float* rh  = (const float*)d_in[1];
    // d_in[2] = Wl, d_in[4] = al: dead (row-constant logit cancels in softmax)
    const float* Wr  = (const float*)d_in[3];
    const float* ar  = (const float*)d_in[5];
    const float* Wrs = (const float*)d_in[6];
    const float* Wrt = (const float*)d_in[7];
    const float* Wf  = (const float*)d_in[8];
    const float* lng = (const float*)d_in[9];
    const float* lnb = (const float*)d_in[10];
    float* out = (float*)d_out;

    float *fr, *rk, *rq, *srb, *ctx, *fh;
    cudaGetSymbolAddress((void**)&fr,  g_fr);
    cudaGetSymbolAddress((void**)&rk,  g_rk);
    cudaGetSymbolAddress((void**)&rq,  g_rq);
    cudaGetSymbolAddress((void**)&srb, g_sr);
    cudaGetSymbolAddress((void**)&ctx, g_ctx);
    cudaGetSymbolAddress((void**)&fh,  g_fh);

    const dim3 gemm_grid(D / 128, M / 128);  // (4, 64)
    gemm_tf32_kernel<512><<<gemm_grid, 256>>>(h, Wr, fr);
    gemm_tf32_kernel<64><<<gemm_grid, 256>>>(rh, Wrs, rk);
    gemm_tf32_kernel<64><<<gemm_grid, 256>>>(rh, Wrt, rq);
    sr_kernel<<<(B * H * S) / 8, 256>>>(fr, ar, srb);

    flash_mma_kernel<<<dim3(S / 128, H, B), 256>>>(rk, rq, fr, srb, ctx);

    gemm_tf32_kernel<512><<<gemm_grid, 256>>>(ctx, Wf, fh);
    ln_kernel<<<M, 256>>>(h, fh, lng, lnb, out);
}

// round 15
// speedup vs baseline: 2.7880x; 1.0375x over previous
#include <cuda_runtime.h>
#include <cuda_fp16.h>
#include <math_constants.h>

namespace {
constexpr int B = 4, S = 2048, D = 512, H = 8, HD = 64;
constexpr int M = B * S;  // 8192 rows
constexpr float SLOPE = 0.01f;
constexpr float LN_EPS = 1e-5f;
// flash smem tile sizes (in 4-byte words)
constexpr int KS_TILE = 64 * 68;   // K tile, fp32 bits (tf32 via HW truncation)
constexpr int VT_TILE = 64 * 36;   // V^T tile, half2 pairs
constexpr int SR_TILE = 64;        // per-key bias
constexpr int FLASH_SMEM_WORDS = 2 * (KS_TILE + VT_TILE + SR_TILE);
constexpr int FLASH_SMEM_BYTES = FLASH_SMEM_WORDS * 4;  // 53760
}

// ---------------- scratch (no allocations allowed) ----------------
__device__ float g_fr[M * D];            // h @ Wr       [B*S, H*HD]
__device__ float g_rk[M * D];            // rh @ Wrs
__device__ float g_rq[M * D];            // rh @ Wrt
__device__ float g_sr[B * H * S];        // leaky(fr).ar
__device__ float g_ctx[M * D];           // attention out
__device__ float g_fh[M * D];            // ctx @ Wf
__device__ unsigned g_vt[B * H * HD * (S / 2)];  // V^T as half2: [(bh*64+d)][tpair]

// ---------------- mma / async helpers ----------------
__device__ __forceinline__ unsigned f2tf32(float f) {
    unsigned u;
    asm("cvt.rna.tf32.f32 %0, %1;" : "=r"(u) : "f"(f));
    return u;
}

__device__ __forceinline__ void mma_tf32(float& d0, float& d1, float& d2, float& d3,
                                         unsigned a0, unsigned a1, unsigned a2, unsigned a3,
                                         unsigned b0, unsigned b1) {
    asm volatile(
        "mma.sync.aligned.m16n8k8.row.col.f32.tf32.tf32.f32 "
        "{%0,%1,%2,%3}, {%4,%5,%6,%7}, {%8,%9}, {%0,%1,%2,%3};"
        : "+f"(d0), "+f"(d1), "+f"(d2), "+f"(d3)
        : "r"(a0), "r"(a1), "r"(a2), "r"(a3), "r"(b0), "r"(b1));
}

__device__ __forceinline__ void mma_f16(float& d0, float& d1, float& d2, float& d3,
                                        unsigned a0, unsigned a1, unsigned a2, unsigned a3,
                                        unsigned b0, unsigned b1) {
    asm volatile(
        "mma.sync.aligned.m16n8k16.row.col.f32.f16.f16.f32 "
        "{%0,%1,%2,%3}, {%4,%5,%6,%7}, {%8,%9}, {%0,%1,%2,%3};"
        : "+f"(d0), "+f"(d1), "+f"(d2), "+f"(d3)
        : "r"(a0), "r"(a1), "r"(a2), "r"(a3), "r"(b0), "r"(b1));
}

#define CP_ASYNC16(dst_u32, src_ptr) \
    asm volatile("cp.async.cg.shared.global [%0], [%1], 16;\n" \
                 :: "r"(dst_u32), "l"(src_ptr) : "memory")
#define CP_COMMIT() asm volatile("cp.async.commit_group;\n" ::: "memory")
#define CP_WAIT(N)  asm volatile("cp.async.wait_group %0;\n" :: "n"(N) : "memory")

__device__ __forceinline__ unsigned smem_u32(const void* p) {
    unsigned a;
    asm("{ .reg .u64 t; cvta.to.shared.u64 t, %1; cvt.u32.u64 %0, t; }" : "=r"(a) : "l"(p));
    return a;
}

// ---------------- tf32 tensor-core GEMM (unchanged from R13 WIN) ----------------
template <int K>
__global__ void __launch_bounds__(256, 1) gemm_tf32_kernel(const float* __restrict__ A,
                                                           const float* __restrict__ W,
                                                           float* __restrict__ C) {
    __shared__ unsigned As[128][36];
    __shared__ unsigned Ws[128][36];
    const int tid = threadIdx.x;
    const int wid = tid >> 5, lane = tid & 31;
    const int g = lane >> 2, tg = lane & 3;
    const int m0 = blockIdx.y * 128, n0 = blockIdx.x * 128;
    const int mw = (wid >> 2) * 64, nw = (wid & 3) * 32;

    float acc[4][4][4] = {};

    for (int k0 = 0; k0 < K; k0 += 32) {
        {
            const int r = tid >> 1;
            const int cb = (tid & 1) * 16;
            const float* ap = A + (size_t)(m0 + r) * K + k0 + cb;
#pragma unroll
            for (int c = 0; c < 16; c += 4) {
                const float4 v = *reinterpret_cast<const float4*>(ap + c);
                As[r][cb + c + 0] = f2tf32(v.x);
                As[r][cb + c + 1] = f2tf32(v.y);
                As[r][cb + c + 2] = f2tf32(v.z);
                As[r][cb + c + 3] = f2tf32(v.w);
            }
        }
        {
            const int kk = tid & 31;
            const int nb = (tid >> 5) * 16;
            const float* wp = W + (size_t)(k0 + kk) * D + n0 + nb;
#pragma unroll
            for (int c = 0; c < 16; c += 4) {
                const float4 v = *reinterpret_cast<const float4*>(wp + c);
                Ws[nb + c + 0][kk] = f2tf32(v.x);
                Ws[nb + c + 1][kk] = f2tf32(v.y);
                Ws[nb + c + 2][kk] = f2tf32(v.z);
                Ws[nb + c + 3][kk] = f2tf32(v.w);
            }
        }
        __syncthreads();
#pragma unroll
        for (int s = 0; s < 4; s++) {
            unsigned af[4][4], bf[4][2];
#pragma unroll
            for (int i = 0; i < 4; i++) {
                af[i][0] = As[mw + 16 * i + g][8 * s + tg];
                af[i][1] = As[mw + 16 * i + g + 8][8 * s + tg];
                af[i][2] = As[mw + 16 * i + g][8 * s + tg + 4];
                af[i][3] = As[mw + 16 * i + g + 8][8 * s + tg + 4];
            }
#pragma unroll
            for (int j = 0; j < 4; j++) {
                bf[j][0] = Ws[nw + 8 * j + g][8 * s + tg];
                bf[j][1] = Ws[nw + 8 * j + g][8 * s + tg + 4];
            }
#pragma unroll
            for (int i = 0; i < 4; i++)
#pragma unroll
                for (int j = 0; j < 4; j++)
                    mma_tf32(acc[i][j][0], acc[i][j][1], acc[i][j][2], acc[i][j][3],
                             af[i][0], af[i][1], af[i][2], af[i][3], bf[j][0], bf[j][1]);
        }
        __syncthreads();
    }
#pragma unroll
    for (int i = 0; i < 4; i++) {
        float* cp0 = C + (size_t)(m0 + mw + 16 * i + g) * D + n0 + nw;
        float* cp1 = cp0 + (size_t)8 * D;
#pragma unroll
        for (int j = 0; j < 4; j++) {
            *reinterpret_cast<float2*>(cp0 + 8 * j + 2 * tg) =
                make_float2(acc[i][j][0], acc[i][j][1]);
            *reinterpret_cast<float2*>(cp1 + 8 * j + 2 * tg) =
                make_float2(acc[i][j][2], acc[i][j][3]);
        }
    }
}

// ---------------- per-key additive bias ----------------
__global__ void __launch_bounds__(256) sr_kernel(const float* __restrict__ fr,
                                                 const float* __restrict__ ar,
                                                 float* __restrict__ srb) {
    const int lane = threadIdx.x & 31;
    const int row = blockIdx.x * 8 + (threadIdx.x >> 5);
    const int b = row / (H * S);
    const int hh = (row / S) % H;
    const int t = row % S;
    const float* p = fr + (b * S + t) * D + hh * HD;
    float acc = 0.f;
#pragma unroll
    for (int d = lane; d < HD; d += 32) {
        float v = p[d];
        v = (v >= 0.f) ? v : SLOPE * v;
        acc += v * ar[d];
    }
#pragma unroll
    for (int o = 16; o; o >>= 1) acc += __shfl_xor_sync(0xffffffffu, acc, o);
    if (lane == 0) srb[row] = acc;
}

// ---------------- V pre-convert + transpose: fr -> g_vt[(bh*64+d)][tpair] ----------------
// Same conversion math the flash kernel used in-loop (done 16x per (b,h) before; now once).
__global__ void __launch_bounds__(256) vconv_kernel(const float* __restrict__ fr,
                                                    unsigned* __restrict__ vt) {
    __shared__ unsigned Vt[64 * 36];
    const int bh = blockIdx.y;            // b*H + h
    const int t0 = blockIdx.x * 64;
    const int b = bh >> 3, h = bh & 7;
    const int tid = threadIdx.x;
    {
        int tp = tid >> 3;                // key pair 0..31
        int dq = (tid & 7) * 8;
        const float* vp = fr + (size_t)(b * S + t0 + 2 * tp) * D + h * HD + dq;
        const float4 e0 = *reinterpret_cast<const float4*>(vp);
        const float4 e1 = *reinterpret_cast<const float4*>(vp + 4);
        const float4 o0 = *reinterpret_cast<const float4*>(vp + D);
        const float4 o1 = *reinterpret_cast<const float4*>(vp + D + 4);
        const float ev[8] = {e0.x, e0.y, e0.z, e0.w, e1.x, e1.y, e1.z, e1.w};
        const float ov[8] = {o0.x, o0.y, o0.z, o0.w, o1.x, o1.y, o1.z, o1.w};
#pragma unroll
        for (int k = 0; k < 8; k++) {
            __half2 hv = __floats2half2_rn(ev[k], ov[k]);
            Vt[(dq + k) * 36 + tp] = *reinterpret_cast<unsigned*>(&hv);
        }
    }
    __syncthreads();
    // coalesced writeback: 4 threads per d-row, 8 uints (32B) each
    const int d = tid >> 2, c = (tid & 3) * 8;
    unsigned* dst = vt + (size_t)(bh * HD + d) * (S / 2) + (t0 >> 1) + c;
    const uint4 w0 = *reinterpret_cast<const uint4*>(&Vt[d * 36 + c]);
    const uint4 w1 = *reinterpret_cast<const uint4*>(&Vt[d * 36 + c + 4]);
    *reinterpret_cast<uint4*>(dst) = w0;
    *reinterpret_cast<uint4*>(dst + 4) = w1;
}

// ---------------- tensor-core flash attention, cp.async double-buffered ----------------
// K staged as raw fp32 bits (HW truncates to tf32 in the mma — RZ vs RNA, error
// negligible at measured rel_err 2.4e-6). V staged from pre-converted g_vt.
__global__ void __launch_bounds__(256) flash_mma_kernel(const float* __restrict__ rk,
                                                        const float* __restrict__ rq,
                                                        const unsigned* __restrict__ vt,
                                                        const float* __restrict__ srb,
                                                        float* __restrict__ ctx) {
    extern __shared__ unsigned sm[];
    unsigned* KsBuf = sm;                       // 2 * KS_TILE
    unsigned* VtBuf = sm + 2 * KS_TILE;         // 2 * VT_TILE
    float* srsBuf = (float*)(sm + 2 * KS_TILE + 2 * VT_TILE);  // 2 * SR_TILE
    const unsigned sbase = smem_u32(sm);

    const int b = blockIdx.z, h = blockIdx.y;
    const int q0 = blockIdx.x * 128;
    const int tid = threadIdx.x;
    const int wid = tid >> 5, lane = tid & 31;
    const int g = lane >> 2, tg = lane & 3;

    const float* sr_base = srb + (size_t)(b * H + h) * S;
    const unsigned* vt_base = vt + (size_t)(b * H + h) * HD * (S / 2);

    // per-thread staging coordinates (fixed across tiles)
    const int kt = tid >> 2;                 // K row 0..63
    const int kc = (tid & 3) * 16;           // K col quarter (floats)
    const int vd = tid >> 2;                 // V d-row 0..63
    const int vc = (tid & 3) * 8;            // V col chunk (uints)

    auto stage = [&](int t0, int buf) {
        {   // K tile: 64 rows x 256B, raw fp32 bits
            const float* src = rq + (size_t)(b * S + t0 + kt) * D + h * HD + kc;
            const unsigned dst = sbase + (unsigned)(buf * KS_TILE + kt * 68 + kc) * 4u;
#pragma unroll
            for (int k = 0; k < 4; k++) CP_ASYNC16(dst + k * 16, src + k * 4);
        }
        {   // V tile: 64 rows x 128B of half2 pairs
            const unsigned* src = vt_base + (size_t)vd * (S / 2) + (t0 >> 1) + vc;
            const unsigned dst = sbase + (unsigned)(2 * KS_TILE + buf * VT_TILE + vd * 36 + vc) * 4u;
            CP_ASYNC16(dst, src);
            CP_ASYNC16(dst + 16, src + 4);
        }
        if (tid < 16) {  // bias: 64 floats
            const unsigned dst = sbase + (unsigned)(2 * KS_TILE + 2 * VT_TILE + buf * SR_TILE + tid * 4) * 4u;
            CP_ASYNC16(dst, sr_base + t0 + tid * 4);
        }
        CP_COMMIT();
    };

    // Q fragments (tf32 RNA), resident for the whole key loop
    unsigned qf[8][4];
    {
        const float* qb = rk + (size_t)(b * S + q0 + wid * 16) * D + h * HD;
#pragma unroll
        for (int kk = 0; kk < 8; kk++) {
            qf[kk][0] = f2tf32(__ldg(qb + g * D + 8 * kk + tg));
            qf[kk][1] = f2tf32(__ldg(qb + (g + 8) * D + 8 * kk + tg));
            qf[kk][2] = f2tf32(__ldg(qb + g * D + 8 * kk + tg + 4));
            qf[kk][3] = f2tf32(__ldg(qb + (g + 8) * D + 8 * kk + tg + 4));
        }
    }

    float oacc[8][4];
#pragma unroll
    for (int j = 0; j < 8; j++)
#pragma unroll
        for (int i = 0; i < 4; i++) oacc[j][i] = 0.f;
    float m0 = -CUDART_INF_F, m1 = -CUDART_INF_F, l0 = 0.f, l1 = 0.f;

    stage(0, 0);

    for (int it = 0; it < S / 64; it++) {
        const int buf = it & 1;
        if (it + 1 < S / 64) {
            stage((it + 1) * 64, buf ^ 1);
            CP_WAIT(1);   // tile `it` complete; tile it+1 may be in flight
        } else {
            CP_WAIT(0);
        }
        __syncthreads();

        const unsigned* Ks_ = KsBuf + buf * KS_TILE;
        const unsigned* Vt_ = VtBuf + buf * VT_TILE;
        const float* srs_ = srsBuf + buf * SR_TILE;

        // ---- S = Q @ K^T ----
        float sf[8][4];
#pragma unroll
        for (int jn = 0; jn < 8; jn++) {
            sf[jn][0] = sf[jn][1] = sf[jn][2] = sf[jn][3] = 0.f;
#pragma unroll
            for (int kk = 0; kk < 8; kk++) {
                const unsigned b0 = Ks_[(8 * jn + g) * 68 + 8 * kk + tg];
                const unsigned b1 = Ks_[(8 * jn + g) * 68 + 8 * kk + tg + 4];
                mma_tf32(sf[jn][0], sf[jn][1], sf[jn][2], sf[jn][3],
                         qf[kk][0], qf[kk][1], qf[kk][2], qf[kk][3], b0, b1);
            }
        }

        // ---- bias + online softmax ----
        float mx0 = -CUDART_INF_F, mx1 = -CUDART_INF_F;
#pragma unroll
        for (int jn = 0; jn < 8; jn++) {
            const float b0 = srs_[8 * jn + 2 * tg];
            const float b1 = srs_[8 * jn + 2 * tg + 1];
            sf[jn][0] += b0; sf[jn][1] += b1;
            sf[jn][2] += b0; sf[jn][3] += b1;
            mx0 = fmaxf(mx0, fmaxf(sf[jn][0], sf[jn][1]));
            mx1 = fmaxf(mx1, fmaxf(sf[jn][2], sf[jn][3]));
        }
#pragma unroll
        for (int o = 1; o < 4; o <<= 1) {
            mx0 = fmaxf(mx0, __shfl_xor_sync(0xffffffffu, mx0, o));
            mx1 = fmaxf(mx1, __shfl_xor_sync(0xffffffffu, mx1, o));
        }
        const float nm0 = fmaxf(m0, mx0), nm1 = fmaxf(m1, mx1);
        const float sc0 = __expf(m0 - nm0), sc1 = __expf(m1 - nm1);
        float rs0 = 0.f, rs1 = 0.f;
#pragma unroll
        for (int jn = 0; jn < 8; jn++) {
            sf[jn][0] = __expf(sf[jn][0] - nm0);
            sf[jn][1] = __expf(sf[jn][1] - nm0);
            sf[jn][2] = __expf(sf[jn][2] - nm1);
            sf[jn][3] = __expf(sf[jn][3] - nm1);
            rs0 += sf[jn][0] + sf[jn][1];
            rs1 += sf[jn][2] + sf[jn][3];
        }
#pragma unroll
        for (int o = 1; o < 4; o <<= 1) {
            rs0 += __shfl_xor_sync(0xffffffffu, rs0, o);
            rs1 += __shfl_xor_sync(0xffffffffu, rs1, o);
        }
        l0 = l0 * sc0 + rs0;
        l1 = l1 * sc1 + rs1;
        m0 = nm0; m1 = nm1;
#pragma unroll
        for (int jn = 0; jn < 8; jn++) {
            oacc[jn][0] *= sc0; oacc[jn][1] *= sc0;
            oacc[jn][2] *= sc1; oacc[jn][3] *= sc1;
        }

        // ---- pack P -> fp16 A-frags (C-frag/A-frag layout identity) ----
        unsigned pa[4][4];
#pragma unroll
        for (int kt2 = 0; kt2 < 4; kt2++) {
            __half2 h0 = __floats2half2_rn(sf[2 * kt2][0], sf[2 * kt2][1]);
            __half2 h1 = __floats2half2_rn(sf[2 * kt2][2], sf[2 * kt2][3]);
            __half2 h2 = __floats2half2_rn(sf[2 * kt2 + 1][0], sf[2 * kt2 + 1][1]);
            __half2 h3 = __floats2half2_rn(sf[2 * kt2 + 1][2], sf[2 * kt2 + 1][3]);
            pa[kt2][0] = *reinterpret_cast<unsigned*>(&h0);
            pa[kt2][1] = *reinterpret_cast<unsigned*>(&h1);
            pa[kt2][2] = *reinterpret_cast<unsigned*>(&h2);
            pa[kt2][3] = *reinterpret_cast<unsigned*>(&h3);
        }

        // ---- O += P @ V ----
#pragma unroll
        for (int jn = 0; jn < 8; jn++) {
#pragma unroll
            for (int kt2 = 0; kt2 < 4; kt2++) {
                const unsigned b0 = Vt_[(8 * jn + g) * 36 + 8 * kt2 + tg];
                const unsigned b1 = Vt_[(8 * jn + g) * 36 + 8 * kt2 + tg + 4];
                mma_f16(oacc[jn][0], oacc[jn][1], oacc[jn][2], oacc[jn][3],
                        pa[kt2][0], pa[kt2][1], pa[kt2][2], pa[kt2][3], b0, b1);
            }
        }
        __syncthreads();   // protect buf before stage(it+2) overwrites it
    }

    const float inv0 = 1.f / l0, inv1 = 1.f / l1;
    float* op = ctx + (size_t)(b * S + q0 + wid * 16 + g) * D + h * HD;
#pragma unroll
    for (int jn = 0; jn < 8; jn++) {
        float2 w0 = make_float2(oacc[jn][0] * inv0, oacc[jn][1] * inv0);
        *reinterpret_cast<float2*>(op + 8 * jn + 2 * tg) = w0;
        float2 w1 = make_float2(oacc[jn][2] * inv1, oacc[jn][3] * inv1);
        *reinterpret_cast<float2*>(op + 8 * D + 8 * jn + 2 * tg) = w1;
    }
}

// ---------------- residual + LayerNorm ----------------
__global__ void __launch_bounds__(256) ln_kernel(const float* __restrict__ hin,
                                                 const float* __restrict__ fh,
                                                 const float* __restrict__ g,
                                                 const float* __restrict__ be,
                                                 float* __restrict__ out) {
    const int row = blockIdx.x;
    const int tid = threadIdx.x;
    const float x0 = hin[row * D + tid] + fh[row * D + tid];
    const float x1 = hin[row * D + tid + 256] + fh[row * D + tid + 256];
    float s = x0 + x1, q = x0 * x0 + x1 * x1;
#pragma unroll
    for (int o = 16; o; o >>= 1) {
        s += __shfl_xor_sync(0xffffffffu, s, o);
        q += __shfl_xor_sync(0xffffffffu, q, o);
    }
    __shared__ float sh_s[8], sh_q[8];
    if ((tid & 31) == 0) { sh_s[tid >> 5] = s; sh_q[tid >> 5] = q; }
    __syncthreads();
    float ts = 0.f, tq = 0.f;
#pragma unroll
    for (int w = 0; w < 8; w++) { ts += sh_s[w]; tq += sh_q[w]; }
    const float mu = ts * (1.f / (float)D);
    const float var = tq * (1.f / (float)D) - mu * mu;
    const float inv = rsqrtf(var + LN_EPS);
    out[row * D + tid] = (x0 - mu) * inv * g[tid] + be[tid];
    out[row * D + tid + 256] = (x1 - mu) * inv * g[tid + 256] + be[tid + 256];
}

// ---------------- launch ----------------
extern "C" void kernel_launch(void* const* d_in, const int* in_sizes, int n_in,
                              void* d_out, int out_size) {
    // metadata order: h, rh, Wl, Wr, al, ar, Wrs, Wrt, Wf, ln_g, ln_b
    const float* h   = (const float*)d_in[0];
    const float* rh  = (const float*)d_in[1];
    // d_in[2] = Wl, d_in[4] = al: dead (row-constant logit cancels in softmax)
    const float* Wr  = (const float*)d_in[3];
    const float* ar  = (const float*)d_in[5];
    const float* Wrs = (const float*)d_in[6];
    const float* Wrt = (const float*)d_in[7];
    const float* Wf  = (const float*)d_in[8];
    const float* lng = (const float*)d_in[9];
    const float* lnb = (const float*)d_in[10];
    float* out = (float*)d_out;

    float *fr, *rk, *rq, *srb, *ctx, *fh;
    unsigned* vt;
    cudaGetSymbolAddress((void**)&fr,  g_fr);
    cudaGetSymbolAddress((void**)&rk,  g_rk);
    cudaGetSymbolAddress((void**)&rq,  g_rq);
    cudaGetSymbolAddress((void**)&srb, g_sr);
    cudaGetSymbolAddress((void**)&ctx, g_ctx);
    cudaGetSymbolAddress((void**)&fh,  g_fh);
    cudaGetSymbolAddress((void**)&vt,  g_vt);

    const dim3 gemm_grid(D / 128, M / 128);  // (4, 64)
    gemm_tf32_kernel<512><<<gemm_grid, 256>>>(h, Wr, fr);
    gemm_tf32_kernel<64><<<gemm_grid, 256>>>(rh, Wrs, rk);
    gemm_tf32_kernel<64><<<gemm_grid, 256>>>(rh, Wrt, rq);
    sr_kernel<<<(B * H * S) / 8, 256>>>(fr, ar, srb);
    vconv_kernel<<<dim3(S / 64, B * H), 256>>>(fr, vt);

    cudaFuncSetAttribute(flash_mma_kernel,
                         cudaFuncAttributeMaxDynamicSharedMemorySize, FLASH_SMEM_BYTES);
    flash_mma_kernel<<<dim3(S / 128, H, B), 256, FLASH_SMEM_BYTES>>>(rk, rq, vt, srb, ctx);

    gemm_tf32_kernel<512><<<gemm_grid, 256>>>(ctx, Wf, fh);
    ln_kernel<<<M, 256>>>(h, fh, lng, lnb, out);
}